// round 5
// baseline (speedup 1.0000x reference)
#include <cuda_runtime.h>
#include <cuda_bf16.h>
#include <cstdint>

// Problem constants (match reference_code)
#define IN_C    128
#define HID_C   256
#define OUT_C   128
#define N_NODES 50000
#define N_EDGES 600000

typedef unsigned long long ull;

// ---------------------------------------------------------------------------
// Scratch (no cudaMalloc allowed): device globals
// ---------------------------------------------------------------------------
__device__ float g_agg1[(size_t)N_NODES * IN_C];   // mean of x over in-edges
__device__ float g_agg2[(size_t)N_NODES * HID_C];  // mean of h over in-edges
__device__ float g_h   [(size_t)N_NODES * HID_C];  // layer-1 output

__device__ int g_cnt_int  [N_NODES];               // in-degree histogram
__device__ int g_row_start[N_NODES + 1];           // CSR row offsets (by dst)
__device__ int g_cursor   [N_NODES];               // fill cursors
__device__ int g_csr_src  [N_EDGES];               // CSR column (src) indices

// ---------------------------------------------------------------------------
// CSR build
// ---------------------------------------------------------------------------
__global__ void zero_int_kernel(int* __restrict__ p, int n)
{
    int i = blockIdx.x * blockDim.x + threadIdx.x;
    if (i < n) p[i] = 0;
}

__global__ void hist_kernel(const int* __restrict__ dst)
{
    int e = blockIdx.x * blockDim.x + threadIdx.x;
    if (e < N_EDGES) atomicAdd(&g_cnt_int[dst[e]], 1);
}

// Single-block exclusive scan of g_cnt_int -> g_row_start
__global__ void scan_kernel()
{
    __shared__ int sdata[1024];
    __shared__ int soffset;
    int tid = threadIdx.x;
    if (tid == 0) soffset = 0;
    __syncthreads();
    for (int base = 0; base < N_NODES; base += 1024) {
        int i = base + tid;
        int v = (i < N_NODES) ? g_cnt_int[i] : 0;
        sdata[tid] = v;
        __syncthreads();
        #pragma unroll
        for (int s = 1; s < 1024; s <<= 1) {
            int t = (tid >= s) ? sdata[tid - s] : 0;
            __syncthreads();
            sdata[tid] += t;
            __syncthreads();
        }
        int incl = sdata[tid];
        if (i < N_NODES) g_row_start[i] = soffset + (incl - v);
        int chunk_total = sdata[1023];
        __syncthreads();
        if (tid == 0) soffset += chunk_total;
        __syncthreads();
    }
    if (tid == 0) g_row_start[N_NODES] = soffset;
}

__global__ void init_cursor_kernel()
{
    int i = blockIdx.x * blockDim.x + threadIdx.x;
    if (i < N_NODES) g_cursor[i] = g_row_start[i];
}

__global__ void fill_kernel(const int* __restrict__ src, const int* __restrict__ dst)
{
    int e = blockIdx.x * blockDim.x + threadIdx.x;
    if (e < N_EDGES) {
        int pos = atomicAdd(&g_cursor[dst[e]], 1);
        g_csr_src[pos] = src[e];
    }
}

// ---------------------------------------------------------------------------
// Gather-aggregate (mean folded in): one warp per node, register accumulators.
// agg[n] = (1/max(deg,1)) * sum over in-neighbors s of feat[s]
// ---------------------------------------------------------------------------
template<int C>
__global__ void gather_kernel(const float* __restrict__ feat,
                              float* __restrict__ agg)
{
    int node = blockIdx.x * (blockDim.x >> 5) + (threadIdx.x >> 5);
    if (node >= N_NODES) return;
    int lane = threadIdx.x & 31;
    int beg = g_row_start[node];
    int end = g_row_start[node + 1];

    constexpr int V = C / 128;            // float4 chunks per lane (1 or 2)
    float4 acc[V];
    #pragma unroll
    for (int v = 0; v < V; v++) acc[v] = make_float4(0.f, 0.f, 0.f, 0.f);

    for (int k = beg; k < end; k++) {
        int s = g_csr_src[k];             // uniform per warp (broadcast load)
        const float4* f = (const float4*)(feat + (size_t)s * C);
        #pragma unroll
        for (int v = 0; v < V; v++) {
            float4 val = f[lane + 32 * v];
            acc[v].x += val.x; acc[v].y += val.y;
            acc[v].z += val.z; acc[v].w += val.w;
        }
    }
    float inv = 1.0f / (float)max(end - beg, 1);
    float4* o = (float4*)(agg + (size_t)node * C);
    #pragma unroll
    for (int v = 0; v < V; v++) {
        acc[v].x *= inv; acc[v].y *= inv; acc[v].z *= inv; acc[v].w *= inv;
        o[lane + 32 * v] = acc[v];
    }
}

// ---------------------------------------------------------------------------
// Packed f32x2 helpers (Blackwell FFMA2 — 2x fp32 throughput, exact fp32)
// ---------------------------------------------------------------------------
__device__ __forceinline__ ull dup_f32(float a) {
    ull r;
    asm("mov.b64 %0, {%1, %1};" : "=l"(r) : "f"(a));
    return r;
}
__device__ __forceinline__ void fma_f32x2(ull& d, ull a, ull b) {
    asm("fma.rn.f32x2 %0, %1, %2, %0;" : "+l"(d) : "l"(a), "l"(b));
}
__device__ __forceinline__ float2 unpack_f32x2(ull v) {
    float lo, hi;
    asm("mov.b64 {%0, %1}, %2;" : "=f"(lo), "=f"(hi) : "l"(v));
    return make_float2(lo, hi);
}

// ---------------------------------------------------------------------------
// Fused SAGE GEMM:  C[M,N] = act( [Aagg | Xroot] @ [Wl ; Wr] + bias )
// (mean already applied inside Aagg by the gather kernel)
// BM=128, BN=128, BK=16, 256 threads, 8x8 per-thread micro-tile via f32x2.
// Thread (tx,ty) owns rows {m0+ty*4+i, m0+64+ty*4+i} and
//                    cols {n0+tx*4+j, n0+64+tx*4+j}, i,j in 0..3.
// ---------------------------------------------------------------------------
template<int K, int N, bool RELU>
__global__ __launch_bounds__(256)
void sage_gemm(const float* __restrict__ Aagg,
               const float* __restrict__ Xroot,
               const float* __restrict__ Wl,
               const float* __restrict__ Wr,
               const float* __restrict__ bias,
               float* __restrict__ Cout,
               int M)
{
    constexpr int BM = 128, BN = 128, BK = 16;
    __shared__ float As[BM][BK + 1];
    __shared__ float Bs[BK][BN];

    int tid = threadIdx.x;
    int tx = tid & 15;        // N direction
    int ty = tid >> 4;        // M direction
    int m0 = blockIdx.x * BM;
    int n0 = blockIdx.y * BN;

    // A-tile load mapping: thread -> rows (a_m, a_m+64), 4 k at a_k
    int a_m = tid >> 2;              // 0..63
    int a_k = (tid & 3) * 4;
    // B-tile load mapping: thread -> rows (b_r, b_r+8), 4 n at b_c
    int b_r = tid >> 5;              // 0..7
    int b_c = (tid & 31) * 4;

    // acc[i][j]: i = row index 0..7 (rows ty*4+i / 64+ty*4+(i-4)),
    //            j = packed col pair 0..3 (cols tx*4+{0,1},{2,3}, 64+tx*4+{0,1},{2,3})
    ull acc[8][4];
    #pragma unroll
    for (int i = 0; i < 8; i++)
        #pragma unroll
        for (int j = 0; j < 4; j++) acc[i][j] = 0ull;  // (+0.f, +0.f)

    #pragma unroll 1
    for (int half = 0; half < 2; half++) {
        const float* A = half ? Xroot : Aagg;
        const float* W = half ? Wr : Wl;
        #pragma unroll 1
        for (int k0 = 0; k0 < K; k0 += BK) {
            // ---- load A tile ----
            #pragma unroll
            for (int rr = 0; rr < 2; rr++) {
                int gm = m0 + a_m + rr * 64;
                float4 av = (gm < M)
                    ? *(const float4*)(A + (size_t)gm * K + k0 + a_k)
                    : make_float4(0.f, 0.f, 0.f, 0.f);
                As[a_m + rr * 64][a_k + 0] = av.x;
                As[a_m + rr * 64][a_k + 1] = av.y;
                As[a_m + rr * 64][a_k + 2] = av.z;
                As[a_m + rr * 64][a_k + 3] = av.w;
            }
            // ---- load B tile ----
            #pragma unroll
            for (int rr = 0; rr < 2; rr++) {
                int br = k0 + b_r + rr * 8;
                float4 bv = *(const float4*)(W + (size_t)br * N + n0 + b_c);
                *(float4*)&Bs[b_r + rr * 8][b_c] = bv;
            }
            __syncthreads();

            #pragma unroll
            for (int k = 0; k < BK; k++) {
                ulonglong2 bq0 = *(const ulonglong2*)&Bs[k][tx * 4];
                ulonglong2 bq1 = *(const ulonglong2*)&Bs[k][64 + tx * 4];
                ull b[4] = {bq0.x, bq0.y, bq1.x, bq1.y};
                ull ad[8];
                #pragma unroll
                for (int i = 0; i < 4; i++) {
                    ad[i]     = dup_f32(As[ty * 4 + i][k]);
                    ad[4 + i] = dup_f32(As[64 + ty * 4 + i][k]);
                }
                #pragma unroll
                for (int i = 0; i < 8; i++)
                    #pragma unroll
                    for (int j = 0; j < 4; j++)
                        fma_f32x2(acc[i][j], ad[i], b[j]);
            }
            __syncthreads();
        }
    }

    // ---- epilogue: + bias, optional relu, float4 stores ----
    float4 bb0 = *(const float4*)(bias + n0 + tx * 4);
    float4 bb1 = *(const float4*)(bias + n0 + 64 + tx * 4);
    #pragma unroll
    for (int i = 0; i < 8; i++) {
        int m = m0 + (i < 4 ? ty * 4 + i : 64 + ty * 4 + (i - 4));
        if (m >= M) continue;
        float2 p0 = unpack_f32x2(acc[i][0]);
        float2 p1 = unpack_f32x2(acc[i][1]);
        float2 p2 = unpack_f32x2(acc[i][2]);
        float2 p3 = unpack_f32x2(acc[i][3]);
        float4 o0 = make_float4(p0.x + bb0.x, p0.y + bb0.y, p1.x + bb0.z, p1.y + bb0.w);
        float4 o1 = make_float4(p2.x + bb1.x, p2.y + bb1.y, p3.x + bb1.z, p3.y + bb1.w);
        if (RELU) {
            o0.x = fmaxf(o0.x, 0.f); o0.y = fmaxf(o0.y, 0.f);
            o0.z = fmaxf(o0.z, 0.f); o0.w = fmaxf(o0.w, 0.f);
            o1.x = fmaxf(o1.x, 0.f); o1.y = fmaxf(o1.y, 0.f);
            o1.z = fmaxf(o1.z, 0.f); o1.w = fmaxf(o1.w, 0.f);
        }
        *(float4*)(Cout + (size_t)m * N + n0 + tx * 4)      = o0;
        *(float4*)(Cout + (size_t)m * N + n0 + 64 + tx * 4) = o1;
    }
}

// ---------------------------------------------------------------------------
// Launch
// ---------------------------------------------------------------------------
extern "C" void kernel_launch(void* const* d_in, const int* in_sizes, int n_in,
                              void* d_out, int out_size)
{
    const float* x   = (const float*)d_in[0];
    const int*   ei  = (const int*)d_in[1];     // int32 (JAX x64 disabled)
    const float* W1l = (const float*)d_in[2];
    const float* b1  = (const float*)d_in[3];
    const float* W1r = (const float*)d_in[4];
    const float* W2l = (const float*)d_in[5];
    const float* b2  = (const float*)d_in[6];
    const float* W2r = (const float*)d_in[7];
    float*       out = (float*)d_out;

    const int* src = ei;
    const int* dst = ei + N_EDGES;

    float *agg1, *agg2, *h;
    int *cnt_int;
    cudaGetSymbolAddress((void**)&agg1,    g_agg1);
    cudaGetSymbolAddress((void**)&agg2,    g_agg2);
    cudaGetSymbolAddress((void**)&h,       g_h);
    cudaGetSymbolAddress((void**)&cnt_int, g_cnt_int);

    // ---- CSR build (shared by both layers) ----
    zero_int_kernel<<<(N_NODES + 255) / 256, 256>>>(cnt_int, N_NODES);
    hist_kernel<<<(N_EDGES + 255) / 256, 256>>>(dst);
    scan_kernel<<<1, 1024>>>();
    init_cursor_kernel<<<(N_NODES + 255) / 256, 256>>>();
    fill_kernel<<<(N_EDGES + 255) / 256, 256>>>(src, dst);

    // ---- layer 1 ----
    {
        int warps_per_block = 8;
        int grid = (N_NODES + warps_per_block - 1) / warps_per_block;
        gather_kernel<IN_C><<<grid, warps_per_block * 32>>>(x, agg1);
    }
    {
        dim3 grid((N_NODES + 127) / 128, HID_C / 128);
        sage_gemm<IN_C, HID_C, true><<<grid, 256>>>(agg1, x, W1l, W1r, b1, h, N_NODES);
    }

    // ---- layer 2 ----
    {
        int warps_per_block = 8;
        int grid = (N_NODES + warps_per_block - 1) / warps_per_block;
        gather_kernel<HID_C><<<grid, warps_per_block * 32>>>(h, agg2);
    }
    {
        dim3 grid((N_NODES + 127) / 128, OUT_C / 128);
        sage_gemm<HID_C, OUT_C, false><<<grid, 256>>>(agg2, h, W2l, W2r, b2, out, N_NODES);
    }
}

// round 7
// speedup vs baseline: 1.4175x; 1.4175x over previous
#include <cuda_runtime.h>
#include <cuda_bf16.h>
#include <cstdint>

// Problem constants (match reference_code)
#define IN_C    128
#define HID_C   256
#define OUT_C   128
#define N_NODES 50000
#define N_EDGES 600000

// ---------------------------------------------------------------------------
// Scratch (no cudaMalloc allowed): device globals
// ---------------------------------------------------------------------------
__device__ float g_agg1[(size_t)N_NODES * IN_C];   // mean of x over in-edges
__device__ float g_agg2[(size_t)N_NODES * HID_C];  // mean of h over in-edges
__device__ float g_h   [(size_t)N_NODES * HID_C];  // layer-1 output

__device__ int g_cnt_int  [N_NODES];
__device__ int g_row_start[N_NODES + 1];
__device__ int g_cursor   [N_NODES];
__device__ int g_csr_src  [N_EDGES];

// Pre-split transposed weights: Wt[n][k] = W[k][n], bf16 hi/lo pair
__device__ __nv_bfloat16 g_wt1_hi[HID_C * (2 * IN_C)];   // [256][256]
__device__ __nv_bfloat16 g_wt1_lo[HID_C * (2 * IN_C)];
__device__ __nv_bfloat16 g_wt2_hi[OUT_C * (2 * HID_C)];  // [128][512]
__device__ __nv_bfloat16 g_wt2_lo[OUT_C * (2 * HID_C)];

// ---------------------------------------------------------------------------
// Helpers
// ---------------------------------------------------------------------------
__device__ __forceinline__ uint32_t smem_to_u32(const void* p) {
    uint32_t a;
    asm("{ .reg .u64 t; cvta.to.shared.u64 t, %1; cvt.u32.u64 %0, t; }" : "=r"(a) : "l"(p));
    return a;
}

#define SMEM_SWIZZLE_128B(off) ((off) ^ (((off) >> 3) & 0x70))

__device__ __forceinline__ void ldsm_x4(uint32_t* r, uint32_t addr) {
    asm volatile("ldmatrix.sync.aligned.m8n8.x4.shared.b16 {%0,%1,%2,%3}, [%4];"
        : "=r"(r[0]), "=r"(r[1]), "=r"(r[2]), "=r"(r[3]) : "r"(addr));
}

__device__ __forceinline__ void mma_bf16(float* c, const uint32_t* a, const uint32_t* b) {
    asm volatile("mma.sync.aligned.m16n8k16.row.col.f32.bf16.bf16.f32 "
        "{%0,%1,%2,%3}, {%4,%5,%6,%7}, {%8,%9}, {%0,%1,%2,%3};"
        : "+f"(c[0]), "+f"(c[1]), "+f"(c[2]), "+f"(c[3])
        : "r"(a[0]), "r"(a[1]), "r"(a[2]), "r"(a[3]), "r"(b[0]), "r"(b[1]));
}

// ---------------------------------------------------------------------------
// CSR build
// ---------------------------------------------------------------------------
__global__ void zero_int_kernel(int* __restrict__ p, int n)
{
    int i = blockIdx.x * blockDim.x + threadIdx.x;
    if (i < n) p[i] = 0;
}

__global__ void hist_kernel(const int* __restrict__ dst)
{
    int e = blockIdx.x * blockDim.x + threadIdx.x;
    if (e < N_EDGES) atomicAdd(&g_cnt_int[dst[e]], 1);
}

__global__ void scan_kernel()
{
    __shared__ int sdata[1024];
    __shared__ int soffset;
    int tid = threadIdx.x;
    if (tid == 0) soffset = 0;
    __syncthreads();
    for (int base = 0; base < N_NODES; base += 1024) {
        int i = base + tid;
        int v = (i < N_NODES) ? g_cnt_int[i] : 0;
        sdata[tid] = v;
        __syncthreads();
        #pragma unroll
        for (int s = 1; s < 1024; s <<= 1) {
            int t = (tid >= s) ? sdata[tid - s] : 0;
            __syncthreads();
            sdata[tid] += t;
            __syncthreads();
        }
        int incl = sdata[tid];
        if (i < N_NODES) g_row_start[i] = soffset + (incl - v);
        int chunk_total = sdata[1023];
        __syncthreads();
        if (tid == 0) soffset += chunk_total;
        __syncthreads();
    }
    if (tid == 0) g_row_start[N_NODES] = soffset;
}

__global__ void init_cursor_kernel()
{
    int i = blockIdx.x * blockDim.x + threadIdx.x;
    if (i < N_NODES) g_cursor[i] = g_row_start[i];
}

__global__ void fill_kernel(const int* __restrict__ src, const int* __restrict__ dst)
{
    int e = blockIdx.x * blockDim.x + threadIdx.x;
    if (e < N_EDGES) {
        int pos = atomicAdd(&g_cursor[dst[e]], 1);
        g_csr_src[pos] = src[e];
    }
}

// ---------------------------------------------------------------------------
// Gather-aggregate (mean folded in): one warp per node
// ---------------------------------------------------------------------------
template<int C>
__global__ void gather_kernel(const float* __restrict__ feat,
                              float* __restrict__ agg)
{
    int node = blockIdx.x * (blockDim.x >> 5) + (threadIdx.x >> 5);
    if (node >= N_NODES) return;
    int lane = threadIdx.x & 31;
    int beg = g_row_start[node];
    int end = g_row_start[node + 1];

    constexpr int V = C / 128;
    float4 acc[V];
    #pragma unroll
    for (int v = 0; v < V; v++) acc[v] = make_float4(0.f, 0.f, 0.f, 0.f);

    for (int k = beg; k < end; k++) {
        int s = g_csr_src[k];
        const float4* f = (const float4*)(feat + (size_t)s * C);
        #pragma unroll
        for (int v = 0; v < V; v++) {
            float4 val = f[lane + 32 * v];
            acc[v].x += val.x; acc[v].y += val.y;
            acc[v].z += val.z; acc[v].w += val.w;
        }
    }
    float inv = 1.0f / (float)max(end - beg, 1);
    float4* o = (float4*)(agg + (size_t)node * C);
    #pragma unroll
    for (int v = 0; v < V; v++) {
        acc[v].x *= inv; acc[v].y *= inv; acc[v].z *= inv; acc[v].w *= inv;
        o[lane + 32 * v] = acc[v];
    }
}

// ---------------------------------------------------------------------------
// Weight prep: transpose [K,N]->[N,K] and split fp32 -> bf16 hi + lo
// ---------------------------------------------------------------------------
template<int K_TOT, int N_TOT>
__global__ void prep_w_kernel(const float* __restrict__ Wa,
                              const float* __restrict__ Wb,
                              __nv_bfloat16* __restrict__ hi,
                              __nv_bfloat16* __restrict__ lo)
{
    int idx = blockIdx.x * blockDim.x + threadIdx.x;
    if (idx >= N_TOT * K_TOT) return;
    int n = idx / K_TOT;
    int k = idx % K_TOT;
    constexpr int Kh = K_TOT / 2;
    float w = (k < Kh) ? Wa[(size_t)k * N_TOT + n] : Wb[(size_t)(k - Kh) * N_TOT + n];
    __nv_bfloat16 h = __float2bfloat16_rn(w);
    float r = w - __bfloat162float(h);
    hi[idx] = h;
    lo[idx] = __float2bfloat16_rn(r);
}

// ---------------------------------------------------------------------------
// Warp-MMA SAGE GEMM:  C[M, N_TOT] = act( [Aagg | Aroot] @ Wt^T + bias )
// bf16 3-term split (hi*hi + lo*hi + hi*lo), fp32 accumulators.
// CTA tile 128(M) x 64(N), 4 warps, warp tile 32x64, K chunks of 64 bf16.
// ---------------------------------------------------------------------------
struct __align__(128) MmaSmem {
    __nv_bfloat16 a_hi[128 * 64];   // 16 KB, SW128 swizzled, 128B rows
    __nv_bfloat16 a_lo[128 * 64];   // 16 KB
    __nv_bfloat16 b_hi[64 * 64];    //  8 KB
    __nv_bfloat16 b_lo[64 * 64];    //  8 KB
};

template<int K_A, int N_TOT, bool RELU>
__global__ __launch_bounds__(128)
void sage_mma_warp(const float* __restrict__ Aagg,
                   const float* __restrict__ Aroot,
                   const __nv_bfloat16* __restrict__ WtHi,
                   const __nv_bfloat16* __restrict__ WtLo,
                   const float* __restrict__ bias,
                   float* __restrict__ Cout,
                   int M)
{
    __shared__ MmaSmem sm;
    constexpr int K_TOT  = 2 * K_A;
    constexpr int CHUNKS = K_TOT / 64;

    int tid  = threadIdx.x;
    int wid  = tid >> 5;          // 0..3, warp m band
    int lane = tid & 31;
    int m0 = blockIdx.x * 128;
    int n0 = blockIdx.y * 64;

    uint32_t sa_hi = smem_to_u32(sm.a_hi);
    uint32_t sa_lo = smem_to_u32(sm.a_lo);
    uint32_t sb_hi = smem_to_u32(sm.b_hi);
    uint32_t sb_lo = smem_to_u32(sm.b_lo);

    // acc[mt][nt][4]: mt in 0..1 (m16 tiles), nt in 0..7 (n8 tiles)
    float acc[2][8][4];
    #pragma unroll
    for (int mt = 0; mt < 2; mt++)
        #pragma unroll
        for (int nt = 0; nt < 8; nt++)
            #pragma unroll
            for (int q = 0; q < 4; q++) acc[mt][nt][q] = 0.f;

    for (int c = 0; c < CHUNKS; c++) {
        // ---- A tile: load fp32, split hi/lo bf16, swizzled STS ----
        {
            const float* Asrc = (c < CHUNKS / 2) ? Aagg : Aroot;
            int k0 = ((c < CHUNKS / 2) ? c : c - CHUNKS / 2) * 64;
            int row = tid;                         // 0..127
            int gm = m0 + row;
            bool valid = gm < M;
            const float* ap = Asrc + (size_t)gm * K_A + k0;
            #pragma unroll
            for (int j = 0; j < 8; j++) {          // 8 x (8 fp32 -> 16B bf16)
                float4 a0, a1;
                if (valid) {
                    a0 = *(const float4*)(ap + j * 8);
                    a1 = *(const float4*)(ap + j * 8 + 4);
                } else {
                    a0 = make_float4(0.f, 0.f, 0.f, 0.f);
                    a1 = a0;
                }
                float v[8] = {a0.x, a0.y, a0.z, a0.w, a1.x, a1.y, a1.z, a1.w};
                unsigned int hp[4], lp[4];
                #pragma unroll
                for (int q = 0; q < 4; q++) {
                    __nv_bfloat16 h0 = __float2bfloat16_rn(v[2 * q]);
                    __nv_bfloat16 h1 = __float2bfloat16_rn(v[2 * q + 1]);
                    float l0f = v[2 * q]     - __bfloat162float(h0);
                    float l1f = v[2 * q + 1] - __bfloat162float(h1);
                    __nv_bfloat16 l0 = __float2bfloat16_rn(l0f);
                    __nv_bfloat16 l1 = __float2bfloat16_rn(l1f);
                    hp[q] = (unsigned int)__bfloat16_as_ushort(h0)
                          | ((unsigned int)__bfloat16_as_ushort(h1) << 16);
                    lp[q] = (unsigned int)__bfloat16_as_ushort(l0)
                          | ((unsigned int)__bfloat16_as_ushort(l1) << 16);
                }
                uint32_t off = SMEM_SWIZZLE_128B((uint32_t)(row * 128 + j * 16));
                *(uint4*)((char*)sm.a_hi + off) = make_uint4(hp[0], hp[1], hp[2], hp[3]);
                *(uint4*)((char*)sm.a_lo + off) = make_uint4(lp[0], lp[1], lp[2], lp[3]);
            }
        }
        // ---- B tile: already bf16 hi/lo, swizzled STS (64 rows x 128B) ----
        {
            int kg = c * 64;
            int row = tid >> 1;                    // 0..63
            int j0  = (tid & 1) * 4;               // chunks j0..j0+3
            const __nv_bfloat16* bh = WtHi + (size_t)(n0 + row) * K_TOT + kg;
            const __nv_bfloat16* bl = WtLo + (size_t)(n0 + row) * K_TOT + kg;
            #pragma unroll
            for (int j = j0; j < j0 + 4; j++) {
                uint4 vh = *(const uint4*)(bh + j * 8);
                uint4 vl = *(const uint4*)(bl + j * 8);
                uint32_t off = SMEM_SWIZZLE_128B((uint32_t)(row * 128 + j * 16));
                *(uint4*)((char*)sm.b_hi + off) = vh;
                *(uint4*)((char*)sm.b_lo + off) = vl;
            }
        }
        __syncthreads();

        // ---- compute: 4 k16-steps per chunk ----
        #pragma unroll
        for (int ks = 0; ks < 4; ks++) {
            // A fragments (hi, lo) for the warp's two m16 tiles
            uint32_t ah[2][4], al[2][4];
            #pragma unroll
            for (int mt = 0; mt < 2; mt++) {
                int r  = wid * 32 + mt * 16 + (lane & 7) + ((lane >> 3) & 1) * 8;
                int cb = ks * 32 + ((lane >> 4) & 1) * 16;
                uint32_t off = SMEM_SWIZZLE_128B((uint32_t)(r * 128 + cb));
                ldsm_x4(ah[mt], sa_hi + off);
                ldsm_x4(al[mt], sa_lo + off);
            }
            #pragma unroll
            for (int half = 0; half < 2; half++) {
                // B fragments (hi, lo) for 4 n8 tiles (2 x4 loads each)
                uint32_t bh[2][4], bl[2][4];
                #pragma unroll
                for (int q = 0; q < 2; q++) {
                    int nt0 = half * 4 + q * 2;           // n-tile pair base
                    int r  = nt0 * 8 + (lane & 7) + ((lane >> 4) & 1) * 8;
                    int cb = ks * 32 + ((lane >> 3) & 1) * 16;
                    uint32_t off = SMEM_SWIZZLE_128B((uint32_t)(r * 128 + cb));
                    ldsm_x4(bh[q], sb_hi + off);
                    ldsm_x4(bl[q], sb_lo + off);
                }
                #pragma unroll
                for (int mt = 0; mt < 2; mt++)
                    #pragma unroll
                    for (int q = 0; q < 2; q++)
                        #pragma unroll
                        for (int sub = 0; sub < 2; sub++) {
                            int nt = half * 4 + q * 2 + sub;
                            mma_bf16(acc[mt][nt], ah[mt], &bh[q][sub * 2]);
                            mma_bf16(acc[mt][nt], al[mt], &bh[q][sub * 2]);
                            mma_bf16(acc[mt][nt], ah[mt], &bl[q][sub * 2]);
                        }
            }
        }
        __syncthreads();
    }

    // ---- epilogue: + bias, optional relu, float2 stores ----
    int g = lane >> 2;
    int t = lane & 3;
    #pragma unroll
    for (int mt = 0; mt < 2; mt++) {
        int r0 = m0 + wid * 32 + mt * 16 + g;
        int r1 = r0 + 8;
        #pragma unroll
        for (int nt = 0; nt < 8; nt++) {
            int n = n0 + nt * 8 + 2 * t;
            float2 bb = *(const float2*)(bias + n);
            float c0 = acc[mt][nt][0] + bb.x;
            float c1 = acc[mt][nt][1] + bb.y;
            float c2 = acc[mt][nt][2] + bb.x;
            float c3 = acc[mt][nt][3] + bb.y;
            if (RELU) {
                c0 = fmaxf(c0, 0.f); c1 = fmaxf(c1, 0.f);
                c2 = fmaxf(c2, 0.f); c3 = fmaxf(c3, 0.f);
            }
            if (r0 < M) *(float2*)(Cout + (size_t)r0 * N_TOT + n) = make_float2(c0, c1);
            if (r1 < M) *(float2*)(Cout + (size_t)r1 * N_TOT + n) = make_float2(c2, c3);
        }
    }
}

// ---------------------------------------------------------------------------
// Launch
// ---------------------------------------------------------------------------
extern "C" void kernel_launch(void* const* d_in, const int* in_sizes, int n_in,
                              void* d_out, int out_size)
{
    const float* x   = (const float*)d_in[0];
    const int*   ei  = (const int*)d_in[1];     // int32 (JAX x64 disabled)
    const float* W1l = (const float*)d_in[2];
    const float* b1  = (const float*)d_in[3];
    const float* W1r = (const float*)d_in[4];
    const float* W2l = (const float*)d_in[5];
    const float* b2  = (const float*)d_in[6];
    const float* W2r = (const float*)d_in[7];
    float*       out = (float*)d_out;

    const int* src = ei;
    const int* dst = ei + N_EDGES;

    float *agg1, *agg2, *h;
    int *cnt_int;
    __nv_bfloat16 *wt1h, *wt1l, *wt2h, *wt2l;
    cudaGetSymbolAddress((void**)&agg1,    g_agg1);
    cudaGetSymbolAddress((void**)&agg2,    g_agg2);
    cudaGetSymbolAddress((void**)&h,       g_h);
    cudaGetSymbolAddress((void**)&cnt_int, g_cnt_int);
    cudaGetSymbolAddress((void**)&wt1h,    g_wt1_hi);
    cudaGetSymbolAddress((void**)&wt1l,    g_wt1_lo);
    cudaGetSymbolAddress((void**)&wt2h,    g_wt2_hi);
    cudaGetSymbolAddress((void**)&wt2l,    g_wt2_lo);

    // ---- CSR build (shared by both layers) ----
    zero_int_kernel<<<(N_NODES + 255) / 256, 256>>>(cnt_int, N_NODES);
    hist_kernel<<<(N_EDGES + 255) / 256, 256>>>(dst);
    scan_kernel<<<1, 1024>>>();
    init_cursor_kernel<<<(N_NODES + 255) / 256, 256>>>();
    fill_kernel<<<(N_EDGES + 255) / 256, 256>>>(src, dst);

    // ---- weight prep (split + transpose) ----
    prep_w_kernel<2 * IN_C,  HID_C><<<(HID_C * 2 * IN_C  + 255) / 256, 256>>>(W1l, W1r, wt1h, wt1l);
    prep_w_kernel<2 * HID_C, OUT_C><<<(OUT_C * 2 * HID_C + 255) / 256, 256>>>(W2l, W2r, wt2h, wt2l);

    int mgrid = (N_NODES + 127) / 128;

    // ---- layer 1 ----
    {
        int warps_per_block = 8;
        int grid = (N_NODES + warps_per_block - 1) / warps_per_block;
        gather_kernel<IN_C><<<grid, warps_per_block * 32>>>(x, agg1);
    }
    {
        dim3 grid(mgrid, HID_C / 64);
        sage_mma_warp<IN_C, HID_C, true><<<grid, 128>>>(agg1, x, wt1h, wt1l, b1, h, N_NODES);
    }

    // ---- layer 2 ----
    {
        int warps_per_block = 8;
        int grid = (N_NODES + warps_per_block - 1) / warps_per_block;
        gather_kernel<HID_C><<<grid, warps_per_block * 32>>>(h, agg2);
    }
    {
        dim3 grid(mgrid, OUT_C / 64);
        sage_mma_warp<HID_C, OUT_C, false><<<grid, 128>>>(agg2, h, wt2h, wt2l, b2, out, N_NODES);
    }
}

// round 8
// speedup vs baseline: 1.4394x; 1.0154x over previous
#include <cuda_runtime.h>
#include <cuda_bf16.h>
#include <cstdint>

// Problem constants (match reference_code)
#define IN_C    128
#define HID_C   256
#define OUT_C   128
#define N_NODES 50000
#define N_EDGES 600000

// ---------------------------------------------------------------------------
// Scratch (no cudaMalloc allowed): device globals
// ---------------------------------------------------------------------------
__device__ int g_cnt_int  [N_NODES];
__device__ int g_row_start[N_NODES + 1];
__device__ int g_cursor   [N_NODES];
__device__ int g_csr_src  [N_EDGES];

// Split bf16 feature pipeline
__device__ __nv_bfloat16 g_x_hi [(size_t)N_NODES * IN_C];
__device__ __nv_bfloat16 g_x_lo [(size_t)N_NODES * IN_C];
__device__ __nv_bfloat16 g_a1_hi[(size_t)N_NODES * IN_C];
__device__ __nv_bfloat16 g_a1_lo[(size_t)N_NODES * IN_C];
__device__ __nv_bfloat16 g_h_hi [(size_t)N_NODES * HID_C];
__device__ __nv_bfloat16 g_h_lo [(size_t)N_NODES * HID_C];
__device__ __nv_bfloat16 g_a2_hi[(size_t)N_NODES * HID_C];
__device__ __nv_bfloat16 g_a2_lo[(size_t)N_NODES * HID_C];

// Pre-split transposed weights: Wt[n][k] = W[k][n], bf16 hi/lo pair
__device__ __nv_bfloat16 g_wt1_hi[HID_C * (2 * IN_C)];
__device__ __nv_bfloat16 g_wt1_lo[HID_C * (2 * IN_C)];
__device__ __nv_bfloat16 g_wt2_hi[OUT_C * (2 * HID_C)];
__device__ __nv_bfloat16 g_wt2_lo[OUT_C * (2 * HID_C)];

// ---------------------------------------------------------------------------
// Helpers
// ---------------------------------------------------------------------------
__device__ __forceinline__ uint32_t smem_to_u32(const void* p) {
    uint32_t a;
    asm("{ .reg .u64 t; cvta.to.shared.u64 t, %1; cvt.u32.u64 %0, t; }" : "=r"(a) : "l"(p));
    return a;
}

#define SMEM_SWIZZLE_128B(off) ((off) ^ (((off) >> 3) & 0x70))

__device__ __forceinline__ void ldsm_x4(uint32_t* r, uint32_t addr) {
    asm volatile("ldmatrix.sync.aligned.m8n8.x4.shared.b16 {%0,%1,%2,%3}, [%4];"
        : "=r"(r[0]), "=r"(r[1]), "=r"(r[2]), "=r"(r[3]) : "r"(addr));
}

__device__ __forceinline__ void mma_bf16(float* c, const uint32_t* a, const uint32_t* b) {
    asm volatile("mma.sync.aligned.m16n8k16.row.col.f32.bf16.bf16.f32 "
        "{%0,%1,%2,%3}, {%4,%5,%6,%7}, {%8,%9}, {%0,%1,%2,%3};"
        : "+f"(c[0]), "+f"(c[1]), "+f"(c[2]), "+f"(c[3])
        : "r"(a[0]), "r"(a[1]), "r"(a[2]), "r"(a[3]), "r"(b[0]), "r"(b[1]));
}

__device__ __forceinline__ void cp_async16(uint32_t smem, const void* g, bool valid) {
    int sz = valid ? 16 : 0;
    asm volatile("cp.async.cg.shared.global [%0], [%1], 16, %2;"
        :: "r"(smem), "l"(g), "r"(sz) : "memory");
}
#define CP_COMMIT() asm volatile("cp.async.commit_group;" ::: "memory")
#define CP_WAIT0()  asm volatile("cp.async.wait_group 0;" ::: "memory")

// split one fp32 into hi/lo bf16
__device__ __forceinline__ void split_f32(float v, __nv_bfloat16& h, __nv_bfloat16& l) {
    h = __float2bfloat16_rn(v);
    l = __float2bfloat16_rn(v - __bfloat162float(h));
}

// ---------------------------------------------------------------------------
// CSR build
// ---------------------------------------------------------------------------
__global__ void zero_int_kernel(int* __restrict__ p, int n)
{
    int i = blockIdx.x * blockDim.x + threadIdx.x;
    if (i < n) p[i] = 0;
}

__global__ void hist_kernel(const int* __restrict__ dst)
{
    int e = blockIdx.x * blockDim.x + threadIdx.x;
    if (e < N_EDGES) atomicAdd(&g_cnt_int[dst[e]], 1);
}

// exclusive scan -> g_row_start; also initializes g_cursor
__global__ void scan_kernel()
{
    __shared__ int sdata[1024];
    __shared__ int soffset;
    int tid = threadIdx.x;
    if (tid == 0) soffset = 0;
    __syncthreads();
    for (int base = 0; base < N_NODES; base += 1024) {
        int i = base + tid;
        int v = (i < N_NODES) ? g_cnt_int[i] : 0;
        sdata[tid] = v;
        __syncthreads();
        #pragma unroll
        for (int s = 1; s < 1024; s <<= 1) {
            int t = (tid >= s) ? sdata[tid - s] : 0;
            __syncthreads();
            sdata[tid] += t;
            __syncthreads();
        }
        int incl = sdata[tid];
        if (i < N_NODES) {
            int excl = soffset + (incl - v);
            g_row_start[i] = excl;
            g_cursor[i]    = excl;
        }
        int chunk_total = sdata[1023];
        __syncthreads();
        if (tid == 0) soffset += chunk_total;
        __syncthreads();
    }
    if (tid == 0) g_row_start[N_NODES] = soffset;
}

__global__ void fill_kernel(const int* __restrict__ src, const int* __restrict__ dst)
{
    int e = blockIdx.x * blockDim.x + threadIdx.x;
    if (e < N_EDGES) {
        int pos = atomicAdd(&g_cursor[dst[e]], 1);
        g_csr_src[pos] = src[e];
    }
}

// ---------------------------------------------------------------------------
// Split fp32 features -> hi/lo bf16 (4 elems per thread)
// ---------------------------------------------------------------------------
__global__ void split_feat_kernel(const float* __restrict__ in,
                                  __nv_bfloat16* __restrict__ hi,
                                  __nv_bfloat16* __restrict__ lo,
                                  int n4)
{
    int i = blockIdx.x * blockDim.x + threadIdx.x;
    if (i >= n4) return;
    float4 v = *(const float4*)(in + i * 4);
    __nv_bfloat16 h0, h1, h2, h3, l0, l1, l2, l3;
    split_f32(v.x, h0, l0); split_f32(v.y, h1, l1);
    split_f32(v.z, h2, l2); split_f32(v.w, h3, l3);
    __nv_bfloat162* ph = (__nv_bfloat162*)(hi + i * 4);
    __nv_bfloat162* pl = (__nv_bfloat162*)(lo + i * 4);
    ph[0] = __nv_bfloat162(h0, h1); ph[1] = __nv_bfloat162(h2, h3);
    pl[0] = __nv_bfloat162(l0, l1); pl[1] = __nv_bfloat162(l2, l3);
}

// ---------------------------------------------------------------------------
// Gather-aggregate on split bf16 features; emits split bf16 aggregate.
// One warp per node; lane owns 4 consecutive columns per 128-col pass.
// ---------------------------------------------------------------------------
template<int C>
__global__ void gather_bf16_kernel(const __nv_bfloat16* __restrict__ fhi,
                                   const __nv_bfloat16* __restrict__ flo,
                                   __nv_bfloat16* __restrict__ ahi,
                                   __nv_bfloat16* __restrict__ alo)
{
    int node = blockIdx.x * (blockDim.x >> 5) + (threadIdx.x >> 5);
    if (node >= N_NODES) return;
    int lane = threadIdx.x & 31;
    int beg = g_row_start[node];
    int end = g_row_start[node + 1];

    constexpr int V = C / 128;
    float4 acc[V];
    #pragma unroll
    for (int v = 0; v < V; v++) acc[v] = make_float4(0.f, 0.f, 0.f, 0.f);

    for (int k = beg; k < end; k++) {
        int s = g_csr_src[k];
        const uint2* ph = (const uint2*)(fhi + (size_t)s * C);
        const uint2* pl = (const uint2*)(flo + (size_t)s * C);
        #pragma unroll
        for (int v = 0; v < V; v++) {
            uint2 hw = ph[lane + 32 * v];
            uint2 lw = pl[lane + 32 * v];
            float2 h0 = __bfloat1622float2(*(__nv_bfloat162*)&hw.x);
            float2 h1 = __bfloat1622float2(*(__nv_bfloat162*)&hw.y);
            float2 l0 = __bfloat1622float2(*(__nv_bfloat162*)&lw.x);
            float2 l1 = __bfloat1622float2(*(__nv_bfloat162*)&lw.y);
            acc[v].x += h0.x + l0.x;
            acc[v].y += h0.y + l0.y;
            acc[v].z += h1.x + l1.x;
            acc[v].w += h1.y + l1.y;
        }
    }
    float inv = 1.0f / (float)max(end - beg, 1);
    #pragma unroll
    for (int v = 0; v < V; v++) {
        float4 a = acc[v];
        a.x *= inv; a.y *= inv; a.z *= inv; a.w *= inv;
        __nv_bfloat16 h0, h1, h2, h3, l0, l1, l2, l3;
        split_f32(a.x, h0, l0); split_f32(a.y, h1, l1);
        split_f32(a.z, h2, l2); split_f32(a.w, h3, l3);
        uint2 hw, lw;
        *(__nv_bfloat162*)&hw.x = __nv_bfloat162(h0, h1);
        *(__nv_bfloat162*)&hw.y = __nv_bfloat162(h2, h3);
        *(__nv_bfloat162*)&lw.x = __nv_bfloat162(l0, l1);
        *(__nv_bfloat162*)&lw.y = __nv_bfloat162(l2, l3);
        ((uint2*)(ahi + (size_t)node * C))[lane + 32 * v] = hw;
        ((uint2*)(alo + (size_t)node * C))[lane + 32 * v] = lw;
    }
}

// ---------------------------------------------------------------------------
// Weight prep: transpose [K,N]->[N,K] and split fp32 -> bf16 hi + lo
// ---------------------------------------------------------------------------
template<int K_TOT, int N_TOT>
__global__ void prep_w_kernel(const float* __restrict__ Wa,
                              const float* __restrict__ Wb,
                              __nv_bfloat16* __restrict__ hi,
                              __nv_bfloat16* __restrict__ lo)
{
    int idx = blockIdx.x * blockDim.x + threadIdx.x;
    if (idx >= N_TOT * K_TOT) return;
    int n = idx / K_TOT;
    int k = idx % K_TOT;
    constexpr int Kh = K_TOT / 2;
    float w = (k < Kh) ? Wa[(size_t)k * N_TOT + n] : Wb[(size_t)(k - Kh) * N_TOT + n];
    __nv_bfloat16 h, l;
    split_f32(w, h, l);
    hi[idx] = h;
    lo[idx] = l;
}

// ---------------------------------------------------------------------------
// Warp-MMA SAGE GEMM on pre-split bf16 inputs.
// C[M, N_TOT] = act( [Aagg | Aroot] @ Wt^T + bias )
// 3-term split (hi*hi + lo*hi + hi*lo), fp32 accumulators.
// CTA tile 128(M) x 64(N), 4 warps, K chunks of 64 bf16, cp.async loads.
// ---------------------------------------------------------------------------
struct __align__(128) MmaSmem {
    __nv_bfloat16 a_hi[128 * 64];   // 16 KB, SW128 swizzled, 128B rows
    __nv_bfloat16 a_lo[128 * 64];   // 16 KB
    __nv_bfloat16 b_hi[64 * 64];    //  8 KB
    __nv_bfloat16 b_lo[64 * 64];    //  8 KB
};

template<int K_A, int N_TOT, bool RELU, bool SPLIT_OUT>
__global__ __launch_bounds__(128)
void sage_mma_warp(const __nv_bfloat16* __restrict__ AaggHi,
                   const __nv_bfloat16* __restrict__ AaggLo,
                   const __nv_bfloat16* __restrict__ ArootHi,
                   const __nv_bfloat16* __restrict__ ArootLo,
                   const __nv_bfloat16* __restrict__ WtHi,
                   const __nv_bfloat16* __restrict__ WtLo,
                   const float* __restrict__ bias,
                   float* __restrict__ Cout,
                   __nv_bfloat16* __restrict__ CoutHi,
                   __nv_bfloat16* __restrict__ CoutLo,
                   int M)
{
    __shared__ MmaSmem sm;
    constexpr int K_TOT  = 2 * K_A;
    constexpr int CHUNKS = K_TOT / 64;

    int tid  = threadIdx.x;
    int wid  = tid >> 5;
    int lane = tid & 31;
    int m0 = blockIdx.x * 128;
    int n0 = blockIdx.y * 64;

    uint32_t sa_hi = smem_to_u32(sm.a_hi);
    uint32_t sa_lo = smem_to_u32(sm.a_lo);
    uint32_t sb_hi = smem_to_u32(sm.b_hi);
    uint32_t sb_lo = smem_to_u32(sm.b_lo);

    float acc[2][8][4];
    #pragma unroll
    for (int mt = 0; mt < 2; mt++)
        #pragma unroll
        for (int nt = 0; nt < 8; nt++)
            #pragma unroll
            for (int q = 0; q < 4; q++) acc[mt][nt][q] = 0.f;

    for (int c = 0; c < CHUNKS; c++) {
        // ---- A tile: cp.async bf16 hi/lo (128 rows x 128B) ----
        {
            bool agg_half = (c < CHUNKS / 2);
            const __nv_bfloat16* Ah = agg_half ? AaggHi : ArootHi;
            const __nv_bfloat16* Al = agg_half ? AaggLo : ArootLo;
            int k0 = (agg_half ? c : c - CHUNKS / 2) * 64;
            int row = tid;
            int gm = m0 + row;
            bool valid = gm < M;
            const __nv_bfloat16* ph = Ah + (size_t)gm * K_A + k0;
            const __nv_bfloat16* pl = Al + (size_t)gm * K_A + k0;
            #pragma unroll
            for (int j = 0; j < 8; j++) {
                uint32_t off = SMEM_SWIZZLE_128B((uint32_t)(row * 128 + j * 16));
                cp_async16(sa_hi + off, ph + j * 8, valid);
                cp_async16(sa_lo + off, pl + j * 8, valid);
            }
        }
        // ---- B tile: cp.async bf16 hi/lo (64 rows x 128B) ----
        {
            int kg = c * 64;
            int row = tid >> 1;
            int j0  = (tid & 1) * 4;
            const __nv_bfloat16* bh = WtHi + (size_t)(n0 + row) * K_TOT + kg;
            const __nv_bfloat16* bl = WtLo + (size_t)(n0 + row) * K_TOT + kg;
            #pragma unroll
            for (int j = j0; j < j0 + 4; j++) {
                uint32_t off = SMEM_SWIZZLE_128B((uint32_t)(row * 128 + j * 16));
                cp_async16(sb_hi + off, bh + j * 8, true);
                cp_async16(sb_lo + off, bl + j * 8, true);
            }
        }
        CP_COMMIT();
        CP_WAIT0();
        __syncthreads();

        // ---- compute: 4 k16-steps per chunk ----
        #pragma unroll
        for (int ks = 0; ks < 4; ks++) {
            uint32_t ah[2][4], al[2][4];
            #pragma unroll
            for (int mt = 0; mt < 2; mt++) {
                int r  = wid * 32 + mt * 16 + (lane & 7) + ((lane >> 3) & 1) * 8;
                int cb = ks * 32 + ((lane >> 4) & 1) * 16;
                uint32_t off = SMEM_SWIZZLE_128B((uint32_t)(r * 128 + cb));
                ldsm_x4(ah[mt], sa_hi + off);
                ldsm_x4(al[mt], sa_lo + off);
            }
            #pragma unroll
            for (int half = 0; half < 2; half++) {
                uint32_t bh[2][4], bl[2][4];
                #pragma unroll
                for (int q = 0; q < 2; q++) {
                    int nt0 = half * 4 + q * 2;
                    int r  = nt0 * 8 + (lane & 7) + ((lane >> 4) & 1) * 8;
                    int cb = ks * 32 + ((lane >> 3) & 1) * 16;
                    uint32_t off = SMEM_SWIZZLE_128B((uint32_t)(r * 128 + cb));
                    ldsm_x4(bh[q], sb_hi + off);
                    ldsm_x4(bl[q], sb_lo + off);
                }
                #pragma unroll
                for (int mt = 0; mt < 2; mt++)
                    #pragma unroll
                    for (int q = 0; q < 2; q++)
                        #pragma unroll
                        for (int sub = 0; sub < 2; sub++) {
                            int nt = half * 4 + q * 2 + sub;
                            mma_bf16(acc[mt][nt], ah[mt], &bh[q][sub * 2]);
                            mma_bf16(acc[mt][nt], al[mt], &bh[q][sub * 2]);
                            mma_bf16(acc[mt][nt], ah[mt], &bl[q][sub * 2]);
                        }
            }
        }
        __syncthreads();
    }

    // ---- epilogue: + bias, optional relu; fp32 or split bf16 stores ----
    int g = lane >> 2;
    int t = lane & 3;
    #pragma unroll
    for (int mt = 0; mt < 2; mt++) {
        int r0 = m0 + wid * 32 + mt * 16 + g;
        int r1 = r0 + 8;
        #pragma unroll
        for (int nt = 0; nt < 8; nt++) {
            int n = n0 + nt * 8 + 2 * t;
            float2 bb = *(const float2*)(bias + n);
            float c0 = acc[mt][nt][0] + bb.x;
            float c1 = acc[mt][nt][1] + bb.y;
            float c2 = acc[mt][nt][2] + bb.x;
            float c3 = acc[mt][nt][3] + bb.y;
            if (RELU) {
                c0 = fmaxf(c0, 0.f); c1 = fmaxf(c1, 0.f);
                c2 = fmaxf(c2, 0.f); c3 = fmaxf(c3, 0.f);
            }
            if (SPLIT_OUT) {
                if (r0 < M) {
                    __nv_bfloat16 h0, h1, l0, l1;
                    split_f32(c0, h0, l0); split_f32(c1, h1, l1);
                    *(__nv_bfloat162*)(CoutHi + (size_t)r0 * N_TOT + n) = __nv_bfloat162(h0, h1);
                    *(__nv_bfloat162*)(CoutLo + (size_t)r0 * N_TOT + n) = __nv_bfloat162(l0, l1);
                }
                if (r1 < M) {
                    __nv_bfloat16 h2, h3, l2, l3;
                    split_f32(c2, h2, l2); split_f32(c3, h3, l3);
                    *(__nv_bfloat162*)(CoutHi + (size_t)r1 * N_TOT + n) = __nv_bfloat162(h2, h3);
                    *(__nv_bfloat162*)(CoutLo + (size_t)r1 * N_TOT + n) = __nv_bfloat162(l2, l3);
                }
            } else {
                if (r0 < M) *(float2*)(Cout + (size_t)r0 * N_TOT + n) = make_float2(c0, c1);
                if (r1 < M) *(float2*)(Cout + (size_t)r1 * N_TOT + n) = make_float2(c2, c3);
            }
        }
    }
}

// ---------------------------------------------------------------------------
// Launch
// ---------------------------------------------------------------------------
extern "C" void kernel_launch(void* const* d_in, const int* in_sizes, int n_in,
                              void* d_out, int out_size)
{
    const float* x   = (const float*)d_in[0];
    const int*   ei  = (const int*)d_in[1];     // int32 (JAX x64 disabled)
    const float* W1l = (const float*)d_in[2];
    const float* b1  = (const float*)d_in[3];
    const float* W1r = (const float*)d_in[4];
    const float* W2l = (const float*)d_in[5];
    const float* b2  = (const float*)d_in[6];
    const float* W2r = (const float*)d_in[7];
    float*       out = (float*)d_out;

    const int* src = ei;
    const int* dst = ei + N_EDGES;

    int* cnt_int;
    __nv_bfloat16 *xhi, *xlo, *a1hi, *a1lo, *hhi, *hlo, *a2hi, *a2lo;
    __nv_bfloat16 *wt1h, *wt1l, *wt2h, *wt2l;
    cudaGetSymbolAddress((void**)&cnt_int, g_cnt_int);
    cudaGetSymbolAddress((void**)&xhi,  g_x_hi);
    cudaGetSymbolAddress((void**)&xlo,  g_x_lo);
    cudaGetSymbolAddress((void**)&a1hi, g_a1_hi);
    cudaGetSymbolAddress((void**)&a1lo, g_a1_lo);
    cudaGetSymbolAddress((void**)&hhi,  g_h_hi);
    cudaGetSymbolAddress((void**)&hlo,  g_h_lo);
    cudaGetSymbolAddress((void**)&a2hi, g_a2_hi);
    cudaGetSymbolAddress((void**)&a2lo, g_a2_lo);
    cudaGetSymbolAddress((void**)&wt1h, g_wt1_hi);
    cudaGetSymbolAddress((void**)&wt1l, g_wt1_lo);
    cudaGetSymbolAddress((void**)&wt2h, g_wt2_hi);
    cudaGetSymbolAddress((void**)&wt2l, g_wt2_lo);

    // ---- CSR build ----
    zero_int_kernel<<<(N_NODES + 255) / 256, 256>>>(cnt_int, N_NODES);
    hist_kernel<<<(N_EDGES + 255) / 256, 256>>>(dst);
    scan_kernel<<<1, 1024>>>();
    fill_kernel<<<(N_EDGES + 255) / 256, 256>>>(src, dst);

    // ---- feature + weight splits ----
    {
        int n4 = N_NODES * IN_C / 4;
        split_feat_kernel<<<(n4 + 255) / 256, 256>>>(x, xhi, xlo, n4);
    }
    prep_w_kernel<2 * IN_C,  HID_C><<<(HID_C * 2 * IN_C  + 255) / 256, 256>>>(W1l, W1r, wt1h, wt1l);
    prep_w_kernel<2 * HID_C, OUT_C><<<(OUT_C * 2 * HID_C + 255) / 256, 256>>>(W2l, W2r, wt2h, wt2l);

    int mgrid = (N_NODES + 127) / 128;

    // ---- layer 1 ----
    {
        int warps_per_block = 8;
        int grid = (N_NODES + warps_per_block - 1) / warps_per_block;
        gather_bf16_kernel<IN_C><<<grid, warps_per_block * 32>>>(xhi, xlo, a1hi, a1lo);
    }
    {
        dim3 grid(mgrid, HID_C / 64);
        sage_mma_warp<IN_C, HID_C, true, true><<<grid, 128>>>(
            a1hi, a1lo, xhi, xlo, wt1h, wt1l, b1, nullptr, hhi, hlo, N_NODES);
    }

    // ---- layer 2 ----
    {
        int warps_per_block = 8;
        int grid = (N_NODES + warps_per_block - 1) / warps_per_block;
        gather_bf16_kernel<HID_C><<<grid, warps_per_block * 32>>>(hhi, hlo, a2hi, a2lo);
    }
    {
        dim3 grid(mgrid, OUT_C / 64);
        sage_mma_warp<HID_C, OUT_C, false, false><<<grid, 128>>>(
            a2hi, a2lo, hhi, hlo, wt2h, wt2l, b2, out, nullptr, nullptr, N_NODES);
    }
}

// round 9
// speedup vs baseline: 1.9839x; 1.3783x over previous
#include <cuda_runtime.h>
#include <cuda_bf16.h>
#include <cstdint>

// Problem constants (match reference_code)
#define IN_C    128
#define HID_C   256
#define OUT_C   128
#define N_NODES 50000
#define N_EDGES 600000

// ---------------------------------------------------------------------------
// Scratch (no cudaMalloc allowed): device globals
// ---------------------------------------------------------------------------
__device__ int g_cnt_int  [N_NODES];
__device__ int g_row_start[N_NODES + 1];
__device__ int g_cursor   [N_NODES];
__device__ int g_csr_src  [N_EDGES];
__device__ int g_bsum     [256];                 // block sums for scan (196 used)

// Split bf16 feature pipeline
__device__ __nv_bfloat16 g_x_hi [(size_t)N_NODES * IN_C];
__device__ __nv_bfloat16 g_x_lo [(size_t)N_NODES * IN_C];
__device__ __nv_bfloat16 g_a1_hi[(size_t)N_NODES * IN_C];
__device__ __nv_bfloat16 g_a1_lo[(size_t)N_NODES * IN_C];
__device__ __nv_bfloat16 g_h_hi [(size_t)N_NODES * HID_C];
__device__ __nv_bfloat16 g_h_lo [(size_t)N_NODES * HID_C];
__device__ __nv_bfloat16 g_a2_hi[(size_t)N_NODES * HID_C];
__device__ __nv_bfloat16 g_a2_lo[(size_t)N_NODES * HID_C];

// Pre-split transposed weights: Wt[n][k] = W[k][n], bf16 hi/lo pair
__device__ __nv_bfloat16 g_wt1_hi[HID_C * (2 * IN_C)];
__device__ __nv_bfloat16 g_wt1_lo[HID_C * (2 * IN_C)];
__device__ __nv_bfloat16 g_wt2_hi[OUT_C * (2 * HID_C)];
__device__ __nv_bfloat16 g_wt2_lo[OUT_C * (2 * HID_C)];

// ---------------------------------------------------------------------------
// Helpers
// ---------------------------------------------------------------------------
__device__ __forceinline__ uint32_t smem_to_u32(const void* p) {
    uint32_t a;
    asm("{ .reg .u64 t; cvta.to.shared.u64 t, %1; cvt.u32.u64 %0, t; }" : "=r"(a) : "l"(p));
    return a;
}

#define SMEM_SWIZZLE_128B(off) ((off) ^ (((off) >> 3) & 0x70))

__device__ __forceinline__ void ldsm_x4(uint32_t* r, uint32_t addr) {
    asm volatile("ldmatrix.sync.aligned.m8n8.x4.shared.b16 {%0,%1,%2,%3}, [%4];"
        : "=r"(r[0]), "=r"(r[1]), "=r"(r[2]), "=r"(r[3]) : "r"(addr));
}

__device__ __forceinline__ void mma_bf16(float* c, const uint32_t* a, const uint32_t* b) {
    asm volatile("mma.sync.aligned.m16n8k16.row.col.f32.bf16.bf16.f32 "
        "{%0,%1,%2,%3}, {%4,%5,%6,%7}, {%8,%9}, {%0,%1,%2,%3};"
        : "+f"(c[0]), "+f"(c[1]), "+f"(c[2]), "+f"(c[3])
        : "r"(a[0]), "r"(a[1]), "r"(a[2]), "r"(a[3]), "r"(b[0]), "r"(b[1]));
}

__device__ __forceinline__ void cp_async16(uint32_t smem, const void* g, bool valid) {
    int sz = valid ? 16 : 0;
    asm volatile("cp.async.cg.shared.global [%0], [%1], 16, %2;"
        :: "r"(smem), "l"(g), "r"(sz) : "memory");
}
#define CP_COMMIT() asm volatile("cp.async.commit_group;" ::: "memory")
#define CP_WAIT(n)  asm volatile("cp.async.wait_group %0;" :: "n"(n) : "memory")

// split one fp32 into hi/lo bf16
__device__ __forceinline__ void split_f32(float v, __nv_bfloat16& h, __nv_bfloat16& l) {
    h = __float2bfloat16_rn(v);
    l = __float2bfloat16_rn(v - __bfloat162float(h));
}

// ---------------------------------------------------------------------------
// CSR build
// ---------------------------------------------------------------------------
__global__ void zero_int_kernel(int* __restrict__ p, int n)
{
    int i = blockIdx.x * blockDim.x + threadIdx.x;
    if (i < n) p[i] = 0;
}

__global__ void hist_kernel(const int* __restrict__ dst)
{
    int e = blockIdx.x * blockDim.x + threadIdx.x;
    if (e < N_EDGES) atomicAdd(&g_cnt_int[dst[e]], 1);
}

// Parallel scan, stage 1: per-block (256 elems) exclusive scan + block sum
__global__ void scan_stage1_kernel()
{
    __shared__ int sdata[256];
    int tid = threadIdx.x;
    int i = blockIdx.x * 256 + tid;
    int v = (i < N_NODES) ? g_cnt_int[i] : 0;
    sdata[tid] = v;
    __syncthreads();
    #pragma unroll
    for (int s = 1; s < 256; s <<= 1) {
        int t = (tid >= s) ? sdata[tid - s] : 0;
        __syncthreads();
        sdata[tid] += t;
        __syncthreads();
    }
    if (i <= N_NODES) ;  // noop
    if (i < N_NODES) g_row_start[i] = sdata[tid] - v;   // exclusive within block
    if (tid == 255) g_bsum[blockIdx.x] = sdata[255];
}

// Stage 2: exclusive scan of block sums (1 block, 256 threads; NB blocks used)
__global__ void scan_stage2_kernel(int nblocks)
{
    __shared__ int sdata[256];
    int tid = threadIdx.x;
    int v = (tid < nblocks) ? g_bsum[tid] : 0;
    sdata[tid] = v;
    __syncthreads();
    #pragma unroll
    for (int s = 1; s < 256; s <<= 1) {
        int t = (tid >= s) ? sdata[tid - s] : 0;
        __syncthreads();
        sdata[tid] += t;
        __syncthreads();
    }
    if (tid < nblocks) g_bsum[tid] = sdata[tid] - v;    // exclusive
    if (tid == 255) g_row_start[N_NODES] = sdata[255];  // total = N_EDGES
}

// Stage 3: add block offsets, init cursors
__global__ void scan_stage3_kernel()
{
    int i = blockIdx.x * blockDim.x + threadIdx.x;
    if (i < N_NODES) {
        int rs = g_row_start[i] + g_bsum[blockIdx.x];
        g_row_start[i] = rs;
        g_cursor[i]    = rs;
    }
}

__global__ void fill_kernel(const int* __restrict__ src, const int* __restrict__ dst)
{
    int e = blockIdx.x * blockDim.x + threadIdx.x;
    if (e < N_EDGES) {
        int pos = atomicAdd(&g_cursor[dst[e]], 1);
        g_csr_src[pos] = src[e];
    }
}

// ---------------------------------------------------------------------------
// Split fp32 features -> hi/lo bf16 (4 elems per thread)
// ---------------------------------------------------------------------------
__global__ void split_feat_kernel(const float* __restrict__ in,
                                  __nv_bfloat16* __restrict__ hi,
                                  __nv_bfloat16* __restrict__ lo,
                                  int n4)
{
    int i = blockIdx.x * blockDim.x + threadIdx.x;
    if (i >= n4) return;
    float4 v = *(const float4*)(in + i * 4);
    __nv_bfloat16 h0, h1, h2, h3, l0, l1, l2, l3;
    split_f32(v.x, h0, l0); split_f32(v.y, h1, l1);
    split_f32(v.z, h2, l2); split_f32(v.w, h3, l3);
    __nv_bfloat162* ph = (__nv_bfloat162*)(hi + i * 4);
    __nv_bfloat162* pl = (__nv_bfloat162*)(lo + i * 4);
    ph[0] = __nv_bfloat162(h0, h1); ph[1] = __nv_bfloat162(h2, h3);
    pl[0] = __nv_bfloat162(l0, l1); pl[1] = __nv_bfloat162(l2, l3);
}

// ---------------------------------------------------------------------------
// Gather-aggregate on split bf16 features; emits split bf16 aggregate.
// ---------------------------------------------------------------------------
template<int C>
__global__ void gather_bf16_kernel(const __nv_bfloat16* __restrict__ fhi,
                                   const __nv_bfloat16* __restrict__ flo,
                                   __nv_bfloat16* __restrict__ ahi,
                                   __nv_bfloat16* __restrict__ alo)
{
    int node = blockIdx.x * (blockDim.x >> 5) + (threadIdx.x >> 5);
    if (node >= N_NODES) return;
    int lane = threadIdx.x & 31;
    int beg = g_row_start[node];
    int end = g_row_start[node + 1];

    constexpr int V = C / 128;
    float4 acc[V];
    #pragma unroll
    for (int v = 0; v < V; v++) acc[v] = make_float4(0.f, 0.f, 0.f, 0.f);

    for (int k = beg; k < end; k++) {
        int s = g_csr_src[k];
        const uint2* ph = (const uint2*)(fhi + (size_t)s * C);
        const uint2* pl = (const uint2*)(flo + (size_t)s * C);
        #pragma unroll
        for (int v = 0; v < V; v++) {
            uint2 hw = ph[lane + 32 * v];
            uint2 lw = pl[lane + 32 * v];
            float2 h0 = __bfloat1622float2(*(__nv_bfloat162*)&hw.x);
            float2 h1 = __bfloat1622float2(*(__nv_bfloat162*)&hw.y);
            float2 l0 = __bfloat1622float2(*(__nv_bfloat162*)&lw.x);
            float2 l1 = __bfloat1622float2(*(__nv_bfloat162*)&lw.y);
            acc[v].x += h0.x + l0.x;
            acc[v].y += h0.y + l0.y;
            acc[v].z += h1.x + l1.x;
            acc[v].w += h1.y + l1.y;
        }
    }
    float inv = 1.0f / (float)max(end - beg, 1);
    #pragma unroll
    for (int v = 0; v < V; v++) {
        float4 a = acc[v];
        a.x *= inv; a.y *= inv; a.z *= inv; a.w *= inv;
        __nv_bfloat16 h0, h1, h2, h3, l0, l1, l2, l3;
        split_f32(a.x, h0, l0); split_f32(a.y, h1, l1);
        split_f32(a.z, h2, l2); split_f32(a.w, h3, l3);
        uint2 hw, lw;
        *(__nv_bfloat162*)&hw.x = __nv_bfloat162(h0, h1);
        *(__nv_bfloat162*)&hw.y = __nv_bfloat162(h2, h3);
        *(__nv_bfloat162*)&lw.x = __nv_bfloat162(l0, l1);
        *(__nv_bfloat162*)&lw.y = __nv_bfloat162(l2, l3);
        ((uint2*)(ahi + (size_t)node * C))[lane + 32 * v] = hw;
        ((uint2*)(alo + (size_t)node * C))[lane + 32 * v] = lw;
    }
}

// ---------------------------------------------------------------------------
// Weight prep: transpose [K,N]->[N,K] and split fp32 -> bf16 hi + lo
// ---------------------------------------------------------------------------
template<int K_TOT, int N_TOT>
__global__ void prep_w_kernel(const float* __restrict__ Wa,
                              const float* __restrict__ Wb,
                              __nv_bfloat16* __restrict__ hi,
                              __nv_bfloat16* __restrict__ lo)
{
    int idx = blockIdx.x * blockDim.x + threadIdx.x;
    if (idx >= N_TOT * K_TOT) return;
    int n = idx / K_TOT;
    int k = idx % K_TOT;
    constexpr int Kh = K_TOT / 2;
    float w = (k < Kh) ? Wa[(size_t)k * N_TOT + n] : Wb[(size_t)(k - Kh) * N_TOT + n];
    __nv_bfloat16 h, l;
    split_f32(w, h, l);
    hi[idx] = h;
    lo[idx] = l;
}

// ---------------------------------------------------------------------------
// Pipelined warp-MMA SAGE GEMM on pre-split bf16 inputs.
// C[M, N_TOT] = act( [Aagg | Aroot] @ Wt^T + bias )
// 3-term split (hi*hi + lo*hi + hi*lo), fp32 accumulators.
// CTA tile 128(M) x 64(N), 8 warps (one m16 tile each), K chunks of 64 bf16.
// 2-stage cp.async pipeline, dynamic SMEM = 2 x 48KB.
// ---------------------------------------------------------------------------
struct __align__(128) MmaStage {
    __nv_bfloat16 a_hi[128 * 64];   // 16 KB, SW128 swizzled, 128B rows
    __nv_bfloat16 a_lo[128 * 64];   // 16 KB
    __nv_bfloat16 b_hi[64 * 64];    //  8 KB
    __nv_bfloat16 b_lo[64 * 64];    //  8 KB
};
#define MMA_SMEM_TOTAL (2 * (int)sizeof(MmaStage))

template<int K_A, int N_TOT, bool RELU, bool SPLIT_OUT>
__global__ __launch_bounds__(256)
void sage_mma_warp(const __nv_bfloat16* __restrict__ AaggHi,
                   const __nv_bfloat16* __restrict__ AaggLo,
                   const __nv_bfloat16* __restrict__ ArootHi,
                   const __nv_bfloat16* __restrict__ ArootLo,
                   const __nv_bfloat16* __restrict__ WtHi,
                   const __nv_bfloat16* __restrict__ WtLo,
                   const float* __restrict__ bias,
                   float* __restrict__ Cout,
                   __nv_bfloat16* __restrict__ CoutHi,
                   __nv_bfloat16* __restrict__ CoutLo,
                   int M)
{
    extern __shared__ char smem_raw[];
    MmaStage* st = (MmaStage*)smem_raw;
    constexpr int K_TOT  = 2 * K_A;
    constexpr int CHUNKS = K_TOT / 64;

    int tid  = threadIdx.x;
    int wid  = tid >> 5;          // 0..7 : warp's m16 tile
    int lane = tid & 31;
    int m0 = blockIdx.x * 128;
    int n0 = blockIdx.y * 64;

    // ---- load issue for chunk c into stage s ----
    auto load_chunk = [&](int c, int s) {
        uint32_t sa_hi = smem_to_u32(st[s].a_hi);
        uint32_t sa_lo = smem_to_u32(st[s].a_lo);
        uint32_t sb_hi = smem_to_u32(st[s].b_hi);
        uint32_t sb_lo = smem_to_u32(st[s].b_lo);
        // A: 128 rows x 128B, hi+lo. 256 threads: row=tid>>1, 4 x 16B each.
        {
            bool agg_half = (c < CHUNKS / 2);
            const __nv_bfloat16* Ah = agg_half ? AaggHi : ArootHi;
            const __nv_bfloat16* Al = agg_half ? AaggLo : ArootLo;
            int k0 = (agg_half ? c : c - CHUNKS / 2) * 64;
            int row = tid >> 1;
            int j0  = (tid & 1) * 4;
            int gm = m0 + row;
            bool valid = gm < M;
            const __nv_bfloat16* ph = Ah + (size_t)gm * K_A + k0;
            const __nv_bfloat16* pl = Al + (size_t)gm * K_A + k0;
            #pragma unroll
            for (int j = j0; j < j0 + 4; j++) {
                uint32_t off = SMEM_SWIZZLE_128B((uint32_t)(row * 128 + j * 16));
                cp_async16(sa_hi + off, ph + j * 8, valid);
                cp_async16(sa_lo + off, pl + j * 8, valid);
            }
        }
        // B: 64 rows x 128B, hi+lo. row=tid>>2, 2 x 16B each.
        {
            int kg = c * 64;
            int row = tid >> 2;
            int j0  = (tid & 3) * 2;
            const __nv_bfloat16* bh = WtHi + (size_t)(n0 + row) * K_TOT + kg;
            const __nv_bfloat16* bl = WtLo + (size_t)(n0 + row) * K_TOT + kg;
            #pragma unroll
            for (int j = j0; j < j0 + 2; j++) {
                uint32_t off = SMEM_SWIZZLE_128B((uint32_t)(row * 128 + j * 16));
                cp_async16(sb_hi + off, bh + j * 8, true);
                cp_async16(sb_lo + off, bl + j * 8, true);
            }
        }
        CP_COMMIT();
    };

    float acc[8][4];
    #pragma unroll
    for (int nt = 0; nt < 8; nt++)
        #pragma unroll
        for (int q = 0; q < 4; q++) acc[nt][q] = 0.f;

    load_chunk(0, 0);

    for (int c = 0; c < CHUNKS; c++) {
        int s = c & 1;
        if (c + 1 < CHUNKS) {
            load_chunk(c + 1, (c + 1) & 1);
            CP_WAIT(1);
        } else {
            CP_WAIT(0);
        }
        __syncthreads();

        uint32_t sa_hi = smem_to_u32(st[s].a_hi);
        uint32_t sa_lo = smem_to_u32(st[s].a_lo);
        uint32_t sb_hi = smem_to_u32(st[s].b_hi);
        uint32_t sb_lo = smem_to_u32(st[s].b_lo);

        #pragma unroll
        for (int ks = 0; ks < 4; ks++) {
            uint32_t ah[4], al[4];
            {
                int r  = wid * 16 + (lane & 7) + ((lane >> 3) & 1) * 8;
                int cb = ks * 32 + ((lane >> 4) & 1) * 16;
                uint32_t off = SMEM_SWIZZLE_128B((uint32_t)(r * 128 + cb));
                ldsm_x4(ah, sa_hi + off);
                ldsm_x4(al, sa_lo + off);
            }
            #pragma unroll
            for (int half = 0; half < 2; half++) {
                uint32_t bh[2][4], bl[2][4];
                #pragma unroll
                for (int q = 0; q < 2; q++) {
                    int nt0 = half * 4 + q * 2;
                    int r  = nt0 * 8 + (lane & 7) + ((lane >> 4) & 1) * 8;
                    int cb = ks * 32 + ((lane >> 3) & 1) * 16;
                    uint32_t off = SMEM_SWIZZLE_128B((uint32_t)(r * 128 + cb));
                    ldsm_x4(bh[q], sb_hi + off);
                    ldsm_x4(bl[q], sb_lo + off);
                }
                #pragma unroll
                for (int q = 0; q < 2; q++)
                    #pragma unroll
                    for (int sub = 0; sub < 2; sub++) {
                        int nt = half * 4 + q * 2 + sub;
                        mma_bf16(acc[nt], ah, &bh[q][sub * 2]);
                        mma_bf16(acc[nt], al, &bh[q][sub * 2]);
                        mma_bf16(acc[nt], ah, &bl[q][sub * 2]);
                    }
            }
        }
        __syncthreads();
    }

    // ---- epilogue: + bias, optional relu; fp32 or split bf16 stores ----
    int g = lane >> 2;
    int t = lane & 3;
    int r0 = m0 + wid * 16 + g;
    int r1 = r0 + 8;
    #pragma unroll
    for (int nt = 0; nt < 8; nt++) {
        int n = n0 + nt * 8 + 2 * t;
        float2 bb = *(const float2*)(bias + n);
        float c0 = acc[nt][0] + bb.x;
        float c1 = acc[nt][1] + bb.y;
        float c2 = acc[nt][2] + bb.x;
        float c3 = acc[nt][3] + bb.y;
        if (RELU) {
            c0 = fmaxf(c0, 0.f); c1 = fmaxf(c1, 0.f);
            c2 = fmaxf(c2, 0.f); c3 = fmaxf(c3, 0.f);
        }
        if (SPLIT_OUT) {
            if (r0 < M) {
                __nv_bfloat16 h0, h1, l0, l1;
                split_f32(c0, h0, l0); split_f32(c1, h1, l1);
                *(__nv_bfloat162*)(CoutHi + (size_t)r0 * N_TOT + n) = __nv_bfloat162(h0, h1);
                *(__nv_bfloat162*)(CoutLo + (size_t)r0 * N_TOT + n) = __nv_bfloat162(l0, l1);
            }
            if (r1 < M) {
                __nv_bfloat16 h2, h3, l2, l3;
                split_f32(c2, h2, l2); split_f32(c3, h3, l3);
                *(__nv_bfloat162*)(CoutHi + (size_t)r1 * N_TOT + n) = __nv_bfloat162(h2, h3);
                *(__nv_bfloat162*)(CoutLo + (size_t)r1 * N_TOT + n) = __nv_bfloat162(l2, l3);
            }
        } else {
            if (r0 < M) *(float2*)(Cout + (size_t)r0 * N_TOT + n) = make_float2(c0, c1);
            if (r1 < M) *(float2*)(Cout + (size_t)r1 * N_TOT + n) = make_float2(c2, c3);
        }
    }
}

// ---------------------------------------------------------------------------
// Launch
// ---------------------------------------------------------------------------
extern "C" void kernel_launch(void* const* d_in, const int* in_sizes, int n_in,
                              void* d_out, int out_size)
{
    const float* x   = (const float*)d_in[0];
    const int*   ei  = (const int*)d_in[1];     // int32 (JAX x64 disabled)
    const float* W1l = (const float*)d_in[2];
    const float* b1  = (const float*)d_in[3];
    const float* W1r = (const float*)d_in[4];
    const float* W2l = (const float*)d_in[5];
    const float* b2  = (const float*)d_in[6];
    const float* W2r = (const float*)d_in[7];
    float*       out = (float*)d_out;

    const int* src = ei;
    const int* dst = ei + N_EDGES;

    int* cnt_int;
    __nv_bfloat16 *xhi, *xlo, *a1hi, *a1lo, *hhi, *hlo, *a2hi, *a2lo;
    __nv_bfloat16 *wt1h, *wt1l, *wt2h, *wt2l;
    cudaGetSymbolAddress((void**)&cnt_int, g_cnt_int);
    cudaGetSymbolAddress((void**)&xhi,  g_x_hi);
    cudaGetSymbolAddress((void**)&xlo,  g_x_lo);
    cudaGetSymbolAddress((void**)&a1hi, g_a1_hi);
    cudaGetSymbolAddress((void**)&a1lo, g_a1_lo);
    cudaGetSymbolAddress((void**)&hhi,  g_h_hi);
    cudaGetSymbolAddress((void**)&hlo,  g_h_lo);
    cudaGetSymbolAddress((void**)&a2hi, g_a2_hi);
    cudaGetSymbolAddress((void**)&a2lo, g_a2_lo);
    cudaGetSymbolAddress((void**)&wt1h, g_wt1_hi);
    cudaGetSymbolAddress((void**)&wt1l, g_wt1_lo);
    cudaGetSymbolAddress((void**)&wt2h, g_wt2_hi);
    cudaGetSymbolAddress((void**)&wt2l, g_wt2_lo);

    cudaFuncSetAttribute(sage_mma_warp<IN_C,  HID_C, true,  true>,
                         cudaFuncAttributeMaxDynamicSharedMemorySize, MMA_SMEM_TOTAL);
    cudaFuncSetAttribute(sage_mma_warp<HID_C, OUT_C, false, false>,
                         cudaFuncAttributeMaxDynamicSharedMemorySize, MMA_SMEM_TOTAL);

    // ---- CSR build (parallel scan) ----
    const int NB = (N_NODES + 255) / 256;       // 196 blocks
    zero_int_kernel<<<NB, 256>>>(cnt_int, N_NODES);
    hist_kernel<<<(N_EDGES + 255) / 256, 256>>>(dst);
    scan_stage1_kernel<<<NB, 256>>>();
    scan_stage2_kernel<<<1, 256>>>(NB);
    scan_stage3_kernel<<<NB, 256>>>();
    fill_kernel<<<(N_EDGES + 255) / 256, 256>>>(src, dst);

    // ---- feature + weight splits ----
    {
        int n4 = N_NODES * IN_C / 4;
        split_feat_kernel<<<(n4 + 255) / 256, 256>>>(x, xhi, xlo, n4);
    }
    prep_w_kernel<2 * IN_C,  HID_C><<<(HID_C * 2 * IN_C  + 255) / 256, 256>>>(W1l, W1r, wt1h, wt1l);
    prep_w_kernel<2 * HID_C, OUT_C><<<(OUT_C * 2 * HID_C + 255) / 256, 256>>>(W2l, W2r, wt2h, wt2l);

    int mgrid = (N_NODES + 127) / 128;

    // ---- layer 1 ----
    {
        int warps_per_block = 8;
        int grid = (N_NODES + warps_per_block - 1) / warps_per_block;
        gather_bf16_kernel<IN_C><<<grid, warps_per_block * 32>>>(xhi, xlo, a1hi, a1lo);
    }
    {
        dim3 grid(mgrid, HID_C / 64);
        sage_mma_warp<IN_C, HID_C, true, true><<<grid, 256, MMA_SMEM_TOTAL>>>(
            a1hi, a1lo, xhi, xlo, wt1h, wt1l, b1, nullptr, hhi, hlo, N_NODES);
    }

    // ---- layer 2 ----
    {
        int warps_per_block = 8;
        int grid = (N_NODES + warps_per_block - 1) / warps_per_block;
        gather_bf16_kernel<HID_C><<<grid, warps_per_block * 32>>>(hhi, hlo, a2hi, a2lo);
    }
    {
        dim3 grid(mgrid, OUT_C / 64);
        sage_mma_warp<HID_C, OUT_C, false, false><<<grid, 256, MMA_SMEM_TOTAL>>>(
            a2hi, a2lo, hhi, hlo, wt2h, wt2l, b2, out, nullptr, nullptr, N_NODES);
    }
}